// round 9
// baseline (speedup 1.0000x reference)
#include <cuda_runtime.h>
#include <cstdint>
#include <cstdio>

// ---------------- problem constants ----------------
#define BB   2
#define DD   32
#define HH   56
#define WW   56
#define CC   96
#define HEADS 3
#define HD   32
#define NN   98          // window tokens = 2*7*7
#define NWIN 1024        // windows per batch = 16*8*8
#define BW   (BB*NWIN)   // 2048 windows
#define TT   (BW*NN)     // 200704 tokens
#define HID  384

// ---------------- scratch (device globals; allocation-free) ----------------
__device__ float g_xw  [(size_t)TT*CC];     // LN1 out (tf32-rounded)
__device__ float g_qkv [(size_t)TT*3*CC];
__device__ float g_ao  [(size_t)TT*CC];     // attn out (tf32-rounded)
__device__ float g_x1  [(size_t)TT*CC];
__device__ float g_h2  [(size_t)TT*CC];     // LN2 out (tf32-rounded)
__device__ float g_hid [(size_t)TT*HID];    // gelu out (tf32-rounded)

// rounded weights: qkv | proj | fc1 | fc2
#define WQKV_OFF 0
#define WPROJ_OFF 27648
#define WFC1_OFF 36864
#define WFC2_OFF 73728
#define WTOT     110592
__device__ float g_wr[WTOT];

__device__ __forceinline__ uint32_t cvt_tf32(float x) {
    uint32_t r;
    asm("cvt.rna.tf32.f32 %0, %1;" : "=r"(r) : "f"(x));
    return r;
}
__device__ __forceinline__ float round_tf32(float x) {
    return __uint_as_float(cvt_tf32(x));
}

// Map window-token index -> spatial token index.
__device__ __forceinline__ int win_to_spatial(int t) {
    int win = t / NN, n = t - win * NN;
    int b  = win >> 10;
    int wi = win & 1023;
    int d0 = wi >> 6, h0 = (wi >> 3) & 7, w0 = wi & 7;
    int dd = n / 49;  int r = n - dd * 49;
    int hh = r / 7;   int ww = r - hh * 7;
    int d = d0 * 2 + dd + 1; if (d >= DD) d -= DD;
    int h = h0 * 7 + hh + 3; if (h >= HH) h -= HH;
    int w = w0 * 7 + ww + 3; if (w >= WW) w -= WW;
    return ((b * DD + d) * HH + h) * WW + w;
}

// ---------------- weight rounding (one-shot, tiny) ----------------
__global__ void round_weights_kernel(const float* __restrict__ qkv_w,
                                     const float* __restrict__ proj_w,
                                     const float* __restrict__ fc1_w,
                                     const float* __restrict__ fc2_w,
                                     float* __restrict__ wr) {
    int i = blockIdx.x * 256 + threadIdx.x;
    if (i < WTOT) {
        float v;
        if      (i < WPROJ_OFF) v = qkv_w[i - WQKV_OFF];
        else if (i < WFC1_OFF)  v = proj_w[i - WPROJ_OFF];
        else if (i < WFC2_OFF)  v = fc1_w[i - WFC1_OFF];
        else                    v = fc2_w[i - WFC2_OFF];
        wr[i] = round_tf32(v);
    }
}

// ---------------- LayerNorm (warp per token, C=96=3*32), tf32-rounded out ----
__global__ void ln_kernel(const float* __restrict__ in,
                          const float* __restrict__ g,
                          const float* __restrict__ bta,
                          float* __restrict__ out, int gather) {
    int t = blockIdx.x * 4 + (threadIdx.x >> 5);
    int lane = threadIdx.x & 31;
    size_t src = gather ? (size_t)win_to_spatial(t) * CC : (size_t)t * CC;
    float x0 = in[src + lane];
    float x1 = in[src + lane + 32];
    float x2 = in[src + lane + 64];
    float s  = x0 + x1 + x2;
    float sq = x0 * x0 + x1 * x1 + x2 * x2;
    #pragma unroll
    for (int o = 16; o; o >>= 1) {
        s  += __shfl_xor_sync(0xffffffffu, s,  o);
        sq += __shfl_xor_sync(0xffffffffu, sq, o);
    }
    float mean = s * (1.0f / 96.0f);
    float var  = sq * (1.0f / 96.0f) - mean * mean;
    float rst  = rsqrtf(var + 1e-5f);
    size_t dst = (size_t)t * CC;
    out[dst + lane]      = round_tf32((x0 - mean) * rst * g[lane]      + bta[lane]);
    out[dst + lane + 32] = round_tf32((x1 - mean) * rst * g[lane + 32] + bta[lane + 32]);
    out[dst + lane + 64] = round_tf32((x2 - mean) * rst * g[lane + 64] + bta[lane + 64]);
}

// ---------------- shared mma helper ----------------
__device__ __forceinline__ void mma_tf32(float* d, const uint32_t* a, const uint32_t* b) {
    asm volatile(
        "mma.sync.aligned.m16n8k8.row.col.f32.tf32.tf32.f32 "
        "{%0,%1,%2,%3}, {%4,%5,%6,%7}, {%8,%9}, {%0,%1,%2,%3};\n"
        : "+f"(d[0]), "+f"(d[1]), "+f"(d[2]), "+f"(d[3])
        : "r"(a[0]), "r"(a[1]), "r"(a[2]), "r"(a[3]),
          "r"(b[0]), "r"(b[1]));
}

// ---------------- tf32 tensor-core GEMM: C[M,Nd] = A[M,K] * W[Nd,K]^T + bias ----
#define GBM 128
#define GBN 64
#define GBK 32
#define SSTR 36

__device__ __forceinline__ void cp16(uint32_t dst_smem, const float* src, bool pred) {
    int sz = pred ? 16 : 0;
    asm volatile("cp.async.ca.shared.global [%0], [%1], 16, %2;\n"
                 :: "r"(dst_smem), "l"(src), "r"(sz));
}

template<int EPI>
__global__ void __launch_bounds__(256)
gemm_kernel(const float* __restrict__ A, const float* __restrict__ Wt,
            const float* __restrict__ bias, float* __restrict__ Cout,
            const float* __restrict__ res, int M, int Nd, int K) {
    __shared__ float As[2][GBM * SSTR];
    __shared__ float Bs[2][GBN * SSTR];

    int tid  = threadIdx.x;
    int lane = tid & 31, warp = tid >> 5;
    int wm = warp >> 1;
    int wn = warp & 1;
    int g  = lane >> 2, l4 = lane & 3;
    int mBase = blockIdx.y * GBM;
    int nBase = blockIdx.x * GBN;

    int lr = tid >> 3;
    int lc = (tid & 7) * 4;

    const float* Ap = A + (size_t)(mBase + lr) * K + lc;
    const float* Bp = Wt + (size_t)(nBase + lr) * K + lc;

    uint32_t asb = (uint32_t)__cvta_generic_to_shared(&As[0][0]);
    uint32_t bsb = (uint32_t)__cvta_generic_to_shared(&Bs[0][0]);

    float acc[2][4][4];
    #pragma unroll
    for (int mt = 0; mt < 2; mt++)
        #pragma unroll
        for (int nt = 0; nt < 4; nt++)
            #pragma unroll
            for (int e = 0; e < 4; e++) acc[mt][nt][e] = 0.0f;

    int nTiles = K / GBK;

    auto prefetch = [&](int s, int kt) {
        uint32_t ad = asb + (uint32_t)(s * GBM * SSTR + lr * SSTR + lc) * 4;
        uint32_t bd = bsb + (uint32_t)(s * GBN * SSTR + lr * SSTR + lc) * 4;
        int kb = kt * GBK;
        #pragma unroll
        for (int i = 0; i < 4; i++)
            cp16(ad + i * 32 * SSTR * 4, Ap + (size_t)i * 32 * K + kb, true);
        #pragma unroll
        for (int i = 0; i < 2; i++)
            cp16(bd + i * 32 * SSTR * 4, Bp + (size_t)i * 32 * K + kb,
                 (nBase + lr + i * 32) < Nd);
        asm volatile("cp.async.commit_group;\n" ::);
    };

    prefetch(0, 0);
    prefetch(1, 1);

    for (int kt = 0; kt < nTiles; kt++) {
        if (kt + 1 < nTiles)
            asm volatile("cp.async.wait_group 1;\n" ::);
        else
            asm volatile("cp.async.wait_group 0;\n" ::);
        __syncthreads();

        int s = kt & 1;
        const float* as = As[s];
        const float* bs = Bs[s];

        #pragma unroll
        for (int kk = 0; kk < GBK; kk += 8) {
            int kq = kk + l4;
            uint32_t af[2][4], bf[4][2];
            #pragma unroll
            for (int mt = 0; mt < 2; mt++) {
                int r = wm * 32 + mt * 16 + g;
                af[mt][0] = __float_as_uint(as[r * SSTR + kq]);
                af[mt][1] = __float_as_uint(as[(r + 8) * SSTR + kq]);
                af[mt][2] = __float_as_uint(as[r * SSTR + kq + 4]);
                af[mt][3] = __float_as_uint(as[(r + 8) * SSTR + kq + 4]);
            }
            #pragma unroll
            for (int nt = 0; nt < 4; nt++) {
                int c = wn * 32 + nt * 8 + g;
                bf[nt][0] = __float_as_uint(bs[c * SSTR + kq]);
                bf[nt][1] = __float_as_uint(bs[c * SSTR + kq + 4]);
            }
            #pragma unroll
            for (int mt = 0; mt < 2; mt++)
                #pragma unroll
                for (int nt = 0; nt < 4; nt++)
                    mma_tf32(acc[mt][nt], af[mt], bf[nt]);
        }
        __syncthreads();
        if (kt + 2 < nTiles) prefetch(s, kt + 2);
    }

    #pragma unroll
    for (int mt = 0; mt < 2; mt++) {
        #pragma unroll
        for (int h = 0; h < 2; h++) {
            int m = mBase + wm * 32 + mt * 16 + g + h * 8;
            size_t dstrow;
            if (EPI == 1) dstrow = (size_t)win_to_spatial(m) * Nd;
            else          dstrow = (size_t)m * Nd;
            #pragma unroll
            for (int nt = 0; nt < 4; nt++) {
                #pragma unroll
                for (int e = 0; e < 2; e++) {
                    int n = nBase + wn * 32 + nt * 8 + 2 * l4 + e;
                    if (n < Nd) {
                        float v = acc[mt][nt][h * 2 + e] + bias[n];
                        if (EPI == 0) {
                            Cout[dstrow + n] = v;
                        } else if (EPI == 1) {
                            Cout[dstrow + n] = res[dstrow + n] + v;
                        } else if (EPI == 2) {
                            float gl = 0.5f * v * (1.0f + erff(v * 0.70710678118654752f));
                            Cout[dstrow + n] = round_tf32(gl);
                        } else {
                            Cout[dstrow + n] = res[dstrow + n] + v;
                        }
                    }
                }
            }
        }
    }
}

// ---------------- tensor-core windowed attention ----------------
// Block per (window, head), 256 threads = 8 warps.
// Pads: M 98->112 (7 m16), Nk 98->104 (13 n8), K=32 (4 k8). PV: K 104 (13 k8).
// smem floats: q[112*36] | k[104*36] | vt[32*108] | S[112*108]
#define AQ_OFF 0
#define AK_OFF 4032
#define AV_OFF 7776
#define AS_OFF 11232
#define ASTR_QK 36
#define ASTR_S  108
#define ATTN_SMEM ((11232 + 112 * 108) * 4)   // 93312 B

__global__ void __launch_bounds__(256)
attn_kernel(const float* __restrict__ qkv, const float* __restrict__ mask,
            float* __restrict__ out) {
    int blk  = blockIdx.x;
    int win  = blk / HEADS;
    int head = blk - win * HEADS;
    int wi   = win & 1023;
    extern __shared__ float sm[];
    float* q  = sm + AQ_OFF;
    float* k  = sm + AK_OFF;
    float* vt = sm + AV_OFF;
    float* S  = sm + AS_OFF;
    int tid = threadIdx.x;
    int lane = tid & 31, warp = tid >> 5;
    int g = lane >> 2, l4 = lane & 3;
    const float scale = 0.17677669529663687f;

    const float* base = qkv + (size_t)(win * NN) * (3 * CC) + head * HD;

    // stage q (112 rows, zero pad), k (104 rows, zero pad) — tf32-rounded
    for (int e = tid; e < 112 * 32; e += 256) {
        int i = e >> 5, d = e & 31;
        q[i * ASTR_QK + d] = (i < NN) ? round_tf32(base[(size_t)i * (3 * CC) + d] * scale) : 0.0f;
    }
    for (int e = tid; e < 104 * 32; e += 256) {
        int i = e >> 5, d = e & 31;
        k[i * ASTR_QK + d] = (i < NN) ? round_tf32(base[(size_t)i * (3 * CC) + CC + d]) : 0.0f;
    }
    // stage v transposed: vt[d][j], zero pad j>=98 (and cols 104..107)
    for (int e = tid; e < 32 * ASTR_S; e += 256) {
        int d = e / ASTR_S, j = e - d * ASTR_S;
        vt[e] = (j < NN) ? round_tf32(base[(size_t)j * (3 * CC) + 2 * CC + d]) : 0.0f;
    }
    __syncthreads();

    // ---- S = q k^T : 7 x 13 = 91 m16n8 tiles over 8 warps ----
    for (int t = warp; t < 91; t += 8) {
        int mt = t / 13, nt = t - mt * 13;
        float acc[4] = {0.f, 0.f, 0.f, 0.f};
        #pragma unroll
        for (int kk = 0; kk < 32; kk += 8) {
            int kq = kk + l4;
            uint32_t af[4], bf[2];
            int r = mt * 16 + g;
            af[0] = __float_as_uint(q[r * ASTR_QK + kq]);
            af[1] = __float_as_uint(q[(r + 8) * ASTR_QK + kq]);
            af[2] = __float_as_uint(q[r * ASTR_QK + kq + 4]);
            af[3] = __float_as_uint(q[(r + 8) * ASTR_QK + kq + 4]);
            int c = nt * 8 + g;
            bf[0] = __float_as_uint(k[c * ASTR_QK + kq]);
            bf[1] = __float_as_uint(k[c * ASTR_QK + kq + 4]);
            mma_tf32(acc, af, bf);
        }
        int r0 = mt * 16 + g, c0 = nt * 8 + 2 * l4;
        S[r0 * ASTR_S + c0]           = acc[0];
        S[r0 * ASTR_S + c0 + 1]       = acc[1];
        S[(r0 + 8) * ASTR_S + c0]     = acc[2];
        S[(r0 + 8) * ASTR_S + c0 + 1] = acc[3];
    }
    __syncthreads();

    // ---- softmax rows (warp per row), mask added inline; P tf32-rounded ----
    const float* mk = mask + (size_t)wi * (NN * NN);
    for (int i = warp; i < NN; i += 8) {
        float mx = -1e30f;
        for (int j = lane; j < NN; j += 32) {
            float v = S[i * ASTR_S + j] + mk[i * NN + j];
            S[i * ASTR_S + j] = v;
            mx = fmaxf(mx, v);
        }
        #pragma unroll
        for (int o = 16; o; o >>= 1) mx = fmaxf(mx, __shfl_xor_sync(0xffffffffu, mx, o));
        float sum = 0.0f;
        for (int j = lane; j < NN; j += 32) {
            float ev = __expf(S[i * ASTR_S + j] - mx);
            S[i * ASTR_S + j] = ev;
            sum += ev;
        }
        #pragma unroll
        for (int o = 16; o; o >>= 1) sum += __shfl_xor_sync(0xffffffffu, sum, o);
        float inv = 1.0f / sum;
        for (int j = lane; j < NN; j += 32)
            S[i * ASTR_S + j] = round_tf32(S[i * ASTR_S + j] * inv);
        // pad cols 98..103 already 0 (q/k pads were zero, softmax never touches them)
    }
    __syncthreads();

    // ---- O = P @ V : 7 m-tiles x 4 n-tiles = 28 tiles over 8 warps ----
    for (int t = warp; t < 28; t += 8) {
        int mt = t >> 2, nt = t & 3;
        float acc[4] = {0.f, 0.f, 0.f, 0.f};
        #pragma unroll
        for (int kt = 0; kt < 13; kt++) {
            int kq = kt * 8 + l4;
            uint32_t af[4], bf[2];
            int r = mt * 16 + g;
            af[0] = __float_as_uint(S[r * ASTR_S + kq]);
            af[1] = __float_as_uint(S[(r + 8) * ASTR_S + kq]);
            af[2] = __float_as_uint(S[r * ASTR_S + kq + 4]);
            af[3] = __float_as_uint(S[(r + 8) * ASTR_S + kq + 4]);
            int c = nt * 8 + g;
            bf[0] = __float_as_uint(vt[c * ASTR_S + kq]);
            bf[1] = __float_as_uint(vt[c * ASTR_S + kq + 4]);
            mma_tf32(acc, af, bf);
        }
        int r0 = mt * 16 + g;
        int c0 = nt * 8 + 2 * l4;
        size_t ob = (size_t)(win * NN) * CC + head * HD;
        if (r0 < NN) {
            out[ob + (size_t)r0 * CC + c0]     = round_tf32(acc[0]);
            out[ob + (size_t)r0 * CC + c0 + 1] = round_tf32(acc[1]);
        }
        if (r0 + 8 < NN) {
            out[ob + (size_t)(r0 + 8) * CC + c0]     = round_tf32(acc[2]);
            out[ob + (size_t)(r0 + 8) * CC + c0 + 1] = round_tf32(acc[3]);
        }
    }
}

// ---------------- launch ----------------
extern "C" void kernel_launch(void* const* d_in, const int* in_sizes, int n_in,
                              void* d_out, int out_size) {
    const float* x      = (const float*)d_in[0];
    const float* mask   = (const float*)d_in[1];
    const float* n1g    = (const float*)d_in[2];
    const float* n1b    = (const float*)d_in[3];
    const float* qkv_w  = (const float*)d_in[4];
    const float* qkv_b  = (const float*)d_in[5];
    const float* proj_w = (const float*)d_in[6];
    const float* proj_b = (const float*)d_in[7];
    const float* n2g    = (const float*)d_in[8];
    const float* n2b    = (const float*)d_in[9];
    const float* fc1_w  = (const float*)d_in[10];
    const float* fc1_b  = (const float*)d_in[11];
    const float* fc2_w  = (const float*)d_in[12];
    const float* fc2_b  = (const float*)d_in[13];
    float* out = (float*)d_out;

    float *xw, *qkvb, *ao, *x1, *h2, *hid, *wr;
    cudaGetSymbolAddress((void**)&xw,   g_xw);
    cudaGetSymbolAddress((void**)&qkvb, g_qkv);
    cudaGetSymbolAddress((void**)&ao,   g_ao);
    cudaGetSymbolAddress((void**)&x1,   g_x1);
    cudaGetSymbolAddress((void**)&h2,   g_h2);
    cudaGetSymbolAddress((void**)&hid,  g_hid);
    cudaGetSymbolAddress((void**)&wr,   g_wr);

    cudaFuncSetAttribute(attn_kernel, cudaFuncAttributeMaxDynamicSharedMemorySize,
                         ATTN_SMEM);

    const int mtiles = TT / GBM;   // 1568

    // 0) round weights to tf32 (tiny)
    round_weights_kernel<<<(WTOT + 255) / 256, 256>>>(qkv_w, proj_w, fc1_w, fc2_w, wr);
    // 1) LN1 + shift + window partition (tf32-rounded out)
    ln_kernel<<<TT / 4, 128>>>(x, n1g, n1b, xw, 1);
    // 2) qkv = xw @ qkv_w^T + qkv_b   (N=288)
    gemm_kernel<0><<<dim3(5, mtiles), 256>>>(xw, wr + WQKV_OFF, qkv_b, qkvb, nullptr,
                                             TT, 3 * CC, CC);
    // 3) windowed attention (tensor-core)
    attn_kernel<<<BW * HEADS, 256, ATTN_SMEM>>>(qkvb, mask, ao);
    // 4) proj + window reverse + unshift + residual(x) -> x1
    gemm_kernel<1><<<dim3(2, mtiles), 256>>>(ao, wr + WPROJ_OFF, proj_b, x1, x,
                                             TT, CC, CC);
    // 5) LN2 (tf32-rounded out)
    ln_kernel<<<TT / 4, 128>>>(x1, n2g, n2b, h2, 0);
    // 6) fc1 + exact GELU (tf32-rounded out)
    gemm_kernel<2><<<dim3(6, mtiles), 256>>>(h2, wr + WFC1_OFF, fc1_b, hid, nullptr,
                                             TT, HID, CC);
    // 7) fc2 + residual(x1) -> out
    gemm_kernel<3><<<dim3(2, mtiles), 256>>>(hid, wr + WFC2_OFF, fc2_b, out, x1,
                                             TT, CC, HID);
}